// round 10
// baseline (speedup 1.0000x reference)
#include <cuda_runtime.h>
#include <cstdint>

// Problem constants (shapes fixed by the dataset)
#define MAXN 100000
#define FDIM 512
#define HID  32
#define MAXE 3200000
#define NC   96            // 3 views * 32 features, interleaved per node

// ---------------- device scratch (static, no allocation) ----------------
__device__ float g_h[MAXN * NC];        // pre-agg activations (layer 1, then layer 2)
__device__ float g_z1[MAXN * NC];       // relu(agg1 + b1)
__device__ float g_d0[MAXN];            // rsqrt(deg) view 0
__device__ float g_d1[MAXN];            // view 1
__device__ float g_d2[MAXN];            // view 2
__device__ int   g_cnt[MAXN];           // histogram
__device__ int   g_rs[MAXN + 1];        // CSR offsets; post-fill: g_rs[i] = END of row i
__device__ int   g_bsums[512];          // scan block sums (needs >= ceil(MAXN/256)=391)
__device__ int   g_src[MAXE];           // CSR column (src node)
__device__ float g_w0[MAXE];            // per-view edge weight; after k_coef: dinv_src * w
__device__ float g_w1[MAXE];
__device__ float g_w2[MAXE];
__device__ int   g_is64;                // 1 if edge_index is int64, 0 if int32

// ---------------- dtype detection for edge_index ----------------
// View the buffer as 32-bit words. For int64 data the odd words are high words
// (all zero; indices < 2^31). For int32 data odd words are real node indices.
__global__ void k_detect(const int* __restrict__ eil, int E) {
    __shared__ int s[256];
    int nprobe = (E < 1024) ? E : 1024;      // probe word pairs [0, nprobe)
    int acc = 0;
    for (int i = threadIdx.x; i < nprobe; i += 256)
        acc |= eil[2 * i + 1];
    s[threadIdx.x] = acc;
    __syncthreads();
    for (int off = 128; off > 0; off >>= 1) {
        if (threadIdx.x < off) s[threadIdx.x] |= s[threadIdx.x + off];
        __syncthreads();
    }
    if (threadIdx.x == 0) g_is64 = (s[0] == 0) ? 1 : 0;
}

__device__ __forceinline__ int load_src(const int* eil, int E, int e) {
    int v = g_is64 ? eil[2 * e] : eil[e];
    if ((unsigned)v >= (unsigned)MAXN) v = 0;   // defensive clamp (no wild atomics)
    return v;
}
__device__ __forceinline__ int load_dst(const int* eil, int E, int e) {
    int v = g_is64 ? eil[2 * (E + e)] : eil[E + e];
    if ((unsigned)v >= (unsigned)MAXN) v = 0;
    return v;
}

// ---------------- small utility kernels ----------------
__global__ void k_zero_cnt(int n) {
    int i = blockIdx.x * blockDim.x + threadIdx.x;
    if (i < n) g_cnt[i] = 0;
}

__global__ void k_hist(const int* __restrict__ eil, int E) {
    int e = blockIdx.x * blockDim.x + threadIdx.x;
    if (e >= E) return;
    int dst = load_dst(eil, E, e);
    atomicAdd(&g_cnt[dst], 1);
}

// ---------------- 3-level exclusive scan over g_cnt -> g_rs (256-thread blocks) ---
__global__ void k_scan_reduce(int n) {
    __shared__ int s[256];
    int i = blockIdx.x * 256 + threadIdx.x;
    s[threadIdx.x] = (i < n) ? g_cnt[i] : 0;
    __syncthreads();
    for (int off = 128; off > 0; off >>= 1) {
        if (threadIdx.x < off) s[threadIdx.x] += s[threadIdx.x + off];
        __syncthreads();
    }
    if (threadIdx.x == 0) g_bsums[blockIdx.x] = s[0];
}

__global__ void k_scan_sums(int nb) {
    int acc = 0;
    for (int i = 0; i < nb; i++) { int v = g_bsums[i]; g_bsums[i] = acc; acc += v; }
}

__global__ void k_scan_blocks(int n) {
    __shared__ int s[256];
    int tid = threadIdx.x;
    int i = blockIdx.x * 256 + tid;
    int v = (i < n) ? g_cnt[i] : 0;
    s[tid] = v;
    __syncthreads();
    for (int off = 1; off < 256; off <<= 1) {
        int t = (tid >= off) ? s[tid - off] : 0;
        __syncthreads();
        s[tid] += t;
        __syncthreads();
    }
    int excl = s[tid] - v + g_bsums[blockIdx.x];
    if (i < n) g_rs[i] = excl;            // exclusive start (pre-fill convention)
    if (i == n - 1) g_rs[n] = excl + v;
}

// ---------------- CSR fill: cursor IS g_rs (becomes row end) ----------------
__global__ void k_fill(const int* __restrict__ eil,
                       const float* __restrict__ ew,
                       const float* __restrict__ em1,
                       const float* __restrict__ em2, int E) {
    int e = blockIdx.x * blockDim.x + threadIdx.x;
    if (e >= E) return;
    int src = load_src(eil, E, e);
    int dst = load_dst(eil, E, e);
    float w0 = ew[e];
    int pos = atomicAdd(&g_rs[dst], 1);   // after kernel: g_rs[dst] = row end
    if ((unsigned)pos < (unsigned)MAXE) { // defensive (cannot exceed if CSR consistent)
        g_src[pos] = src;
        g_w0[pos] = w0;
        g_w1[pos] = w0 * em1[e];
        g_w2[pos] = w0 * em2[e];
    }
}

// ---------------- per-view degree -> dinv (warp per node) ----------------
__global__ void k_dinv(int nn) {
    int gt = blockIdx.x * blockDim.x + threadIdx.x;
    int node = gt >> 5, lane = gt & 31;
    if (node >= nn) return;
    int s0 = (node == 0) ? 0 : g_rs[node - 1];
    int s1 = g_rs[node];
    float a0 = 0.f, a1 = 0.f, a2 = 0.f;
    for (int p = s0 + lane; p < s1; p += 32) {
        a0 += g_w0[p];
        a1 += g_w1[p];
        a2 += g_w2[p];
    }
    for (int off = 16; off > 0; off >>= 1) {
        a0 += __shfl_xor_sync(0xffffffffu, a0, off);
        a1 += __shfl_xor_sync(0xffffffffu, a1, off);
        a2 += __shfl_xor_sync(0xffffffffu, a2, off);
    }
    if (lane == 0) {
        g_d0[node] = rsqrtf(a0 + 1.0f);
        g_d1[node] = rsqrtf(a1 + 1.0f);
        g_d2[node] = rsqrtf(a2 + 1.0f);
    }
}

// ---------------- fold dinv[src] into stored edge weights ----------------
__global__ void k_coef(int totE) {
    int p = blockIdx.x * blockDim.x + threadIdx.x;
    if (p >= totE) return;
    int s = g_src[p];
    g_w0[p] *= g_d0[s];
    g_w1[p] *= g_d1[s];
    g_w2[p] *= g_d2[s];
}

// ---------------- GEMM1: g_h[N][96] = x[N][512] @ Wc[512][96] ----------------
// Wc columns: [0:32)=W1, [32:64)=fm1*W1, [64:96)=fm2*W1 (mask along K rows).
// 256 threads, CTA tile 128x96, k-step 32, microtile 8x6, scalar loads only.
__global__ __launch_bounds__(256) void k_gemm1(const float* __restrict__ x,
                                               const float* __restrict__ W1,
                                               const float* __restrict__ fm1,
                                               const float* __restrict__ fm2,
                                               int M) {
    __shared__ float As[32][129];   // [k][row], padded: conflict-free
    __shared__ float Bs[32][NC];    // [k][col]
    int t = threadIdx.x;
    int mi = t & 15, ni = t >> 4;
    int rowbase = blockIdx.x * 128;

    float acc[8][6];
    for (int i = 0; i < 8; i++)
        for (int j = 0; j < 6; j++) acc[i][j] = 0.f;

    for (int k0 = 0; k0 < FDIM; k0 += 32) {
        // load A tile 128x32, scalar, coalesced along k
        for (int i = 0; i < 16; i++) {
            int idx = t + i * 256;        // 0..4095
            int r = idx >> 5;             // 0..127
            int k = idx & 31;             // 0..31
            int row = rowbase + r;
            As[k][r] = (row < M) ? x[(size_t)row * FDIM + k0 + k] : 0.f;
        }
        // build B tile 32x96 (mask applied along K rows)
        for (int i = 0; i < 12; i++) {
            int idx = t + i * 256;
            int kk = idx / NC, c = idx - kk * NC;
            int v = c >> 5;
            float m = (v == 0) ? 1.f : ((v == 1) ? fm1[k0 + kk] : fm2[k0 + kk]);
            Bs[kk][c] = m * W1[(k0 + kk) * HID + (c & 31)];
        }
        __syncthreads();
        for (int kk = 0; kk < 32; kk++) {
            float a[8], b[6];
            for (int i = 0; i < 8; i++) a[i] = As[kk][i * 16 + mi];
            for (int j = 0; j < 6; j++) b[j] = Bs[kk][ni * 6 + j];
            for (int i = 0; i < 8; i++)
                for (int j = 0; j < 6; j++)
                    acc[i][j] = fmaf(a[i], b[j], acc[i][j]);
        }
        __syncthreads();
    }
    for (int i = 0; i < 8; i++) {
        int row = rowbase + i * 16 + mi;
        if (row < M) {
            float* op = g_h + (size_t)row * NC + ni * 6;
            for (int j = 0; j < 6; j++) op[j] = acc[i][j];
        }
    }
}

// ---------------- GEMM2: g_h[n][v*32+j] = sum_jp g_z1[n][v*32+jp] * W2[jp][j] ------
__global__ __launch_bounds__(256) void k_gemm2(const float* __restrict__ W2, int nn) {
    __shared__ float W2s[HID * HID];
    __shared__ float zs[32 * NC];
    int t = threadIdx.x;
    for (int i = t; i < HID * HID; i += 256) W2s[i] = W2[i];
    int nbase = blockIdx.x * 32;
    for (int i = t; i < 32 * NC; i += 256) {
        int ln = i / NC, c = i - ln * NC;
        int row = nbase + ln;
        zs[i] = (row < nn) ? g_z1[(size_t)row * NC + c] : 0.f;
    }
    __syncthreads();
    for (int i = t; i < 32 * NC; i += 256) {
        int ln = i / NC, col = i - ln * NC;
        int v = col >> 5, j = col & 31;
        float acc = 0.f;
        for (int jp = 0; jp < HID; jp++)
            acc += zs[ln * NC + v * 32 + jp] * W2s[jp * HID + j];
        int row = nbase + ln;
        if (row < nn) g_h[(size_t)row * NC + col] = acc;
    }
}

// ---------------- aggregation layer 1: g_z1 = relu(agg(g_h) + b1), [n][96] -------
__global__ __launch_bounds__(256) void k_agg1(const float* __restrict__ bias, int nn) {
    int gt = blockIdx.x * blockDim.x + threadIdx.x;
    int node = gt >> 5, lane = gt & 31;
    if (node >= nn) return;
    int s0 = (node == 0) ? 0 : g_rs[node - 1];
    int s1 = g_rs[node];
    float a0 = 0.f, a1 = 0.f, a2 = 0.f;
    for (int p = s0; p < s1; p++) {
        int s = g_src[p];                         // broadcast
        const float* hp = g_h + (size_t)s * NC;
        a0 += g_w0[p] * hp[lane];
        a1 += g_w1[p] * hp[32 + lane];
        a2 += g_w2[p] * hp[64 + lane];
    }
    float d0 = g_d0[node], d1 = g_d1[node], d2 = g_d2[node];
    const float* hd = g_h + (size_t)node * NC;
    float b = bias[lane];
    float r0 = fmaxf(d0 * a0 + d0 * d0 * hd[lane]      + b, 0.f);
    float r1 = fmaxf(d1 * a1 + d1 * d1 * hd[32 + lane] + b, 0.f);
    float r2 = fmaxf(d2 * a2 + d2 * d2 * hd[64 + lane] + b, 0.f);
    g_z1[(size_t)node * NC + lane]      = r0;
    g_z1[(size_t)node * NC + 32 + lane] = r1;
    g_z1[(size_t)node * NC + 64 + lane] = r2;
}

// ---------------- aggregation layer 2: d_out = relu(agg(g_h) + b2), [v][n][32] ----
__global__ __launch_bounds__(256) void k_agg2(const float* __restrict__ bias,
                                              float* __restrict__ dout, int nn) {
    int gt = blockIdx.x * blockDim.x + threadIdx.x;
    int node = gt >> 5, lane = gt & 31;
    if (node >= nn) return;
    int s0 = (node == 0) ? 0 : g_rs[node - 1];
    int s1 = g_rs[node];
    float a0 = 0.f, a1 = 0.f, a2 = 0.f;
    for (int p = s0; p < s1; p++) {
        int s = g_src[p];
        const float* hp = g_h + (size_t)s * NC;
        a0 += g_w0[p] * hp[lane];
        a1 += g_w1[p] * hp[32 + lane];
        a2 += g_w2[p] * hp[64 + lane];
    }
    float d0 = g_d0[node], d1 = g_d1[node], d2 = g_d2[node];
    const float* hd = g_h + (size_t)node * NC;
    float b = bias[lane];
    float r0 = fmaxf(d0 * a0 + d0 * d0 * hd[lane]      + b, 0.f);
    float r1 = fmaxf(d1 * a1 + d1 * d1 * hd[32 + lane] + b, 0.f);
    float r2 = fmaxf(d2 * a2 + d2 * d2 * hd[64 + lane] + b, 0.f);
    size_t stride = (size_t)nn * 32;
    dout[0 * stride + (size_t)node * 32 + lane] = r0;
    dout[1 * stride + (size_t)node * 32 + lane] = r1;
    dout[2 * stride + (size_t)node * 32 + lane] = r2;
}

// ---------------- host orchestration ----------------
extern "C" void kernel_launch(void* const* d_in, const int* in_sizes, int n_in,
                              void* d_out, int out_size) {
    const float* x   = (const float*)d_in[0];
    const int*   eil = (const int*)d_in[1];     // edge_index as 32-bit words (dtype detected)
    const float* ew  = (const float*)d_in[2];
    const float* em1 = (const float*)d_in[3];
    const float* em2 = (const float*)d_in[4];
    const float* fm1 = (const float*)d_in[5];
    const float* fm2 = (const float*)d_in[6];
    const float* W1  = (const float*)d_in[7];
    const float* b1  = (const float*)d_in[8];
    const float* W2  = (const float*)d_in[9];
    const float* b2  = (const float*)d_in[10];
    float* out = (float*)d_out;

    int E  = in_sizes[2];              // edge_weight element count
    int nn = in_sizes[0] / FDIM;       // num nodes

    int eb  = (E + 255) / 256;
    int nb  = (nn + 255) / 256;
    int wb  = (nn * 32 + 255) / 256;   // warp-per-node grids

    // --- detect edge_index dtype, then CSR build ---
    k_detect<<<1, 256>>>(eil, E);
    k_zero_cnt<<<nb, 256>>>(nn);
    k_hist<<<eb, 256>>>(eil, E);
    k_scan_reduce<<<nb, 256>>>(nn);
    k_scan_sums<<<1, 1>>>(nb);
    k_scan_blocks<<<nb, 256>>>(nn);
    k_fill<<<eb, 256>>>(eil, ew, em1, em2, E);

    // --- degrees / dinv, then fold dinv[src] into weights ---
    k_dinv<<<wb, 256>>>(nn);
    k_coef<<<eb, 256>>>(E);

    // --- layer 1 ---
    k_gemm1<<<(nn + 127) / 128, 256>>>(x, W1, fm1, fm2, nn);
    k_agg1<<<wb, 256>>>(b1, nn);

    // --- layer 2 ---
    k_gemm2<<<(nn + 31) / 32, 256>>>(W2, nn);
    k_agg2<<<wb, 256>>>(b2, out, nn);
}

// round 13
// speedup vs baseline: 1.1237x; 1.1237x over previous
#include <cuda_runtime.h>
#include <cstdint>

// Problem constants (shapes fixed by the dataset)
#define MAXN 100000
#define FDIM 512
#define HID  32
#define MAXE 3200000
#define NC   96            // 3 views * 32 features, interleaved per node

// ---------------- device scratch (static, no allocation) ----------------
__device__ float g_h[MAXN * NC];        // pre-agg activations (layer 1, then layer 2)
__device__ float g_z1[MAXN * NC];       // relu(agg1 + b1)
__device__ float g_d0[MAXN];            // rsqrt(deg) view 0
__device__ float g_d1[MAXN];            // view 1
__device__ float g_d2[MAXN];            // view 2
__device__ int   g_cnt[MAXN];           // histogram
__device__ int   g_rs[MAXN + 1];        // CSR offsets; post-fill: g_rs[i] = END of row i
__device__ int   g_bsums[512];          // scan block sums (needs >= ceil(MAXN/256)=391)
__device__ int4  g_ent[MAXE];           // {src, w0_bits, w1_bits, w2_bits}; after k_coef: w *= dinv[src]
__device__ int   g_is64;                // 1 if edge_index is int64, 0 if int32

// ---------------- dtype detection for edge_index ----------------
// View the buffer as 32-bit words. For int64 data the odd words are high words
// (all zero; indices < 2^31). For int32 data odd words are real node indices.
__global__ void k_detect(const int* __restrict__ eil, int E) {
    __shared__ int s[256];
    int nprobe = (E < 1024) ? E : 1024;
    int acc = 0;
    for (int i = threadIdx.x; i < nprobe; i += 256)
        acc |= eil[2 * i + 1];
    s[threadIdx.x] = acc;
    __syncthreads();
    for (int off = 128; off > 0; off >>= 1) {
        if (threadIdx.x < off) s[threadIdx.x] |= s[threadIdx.x + off];
        __syncthreads();
    }
    if (threadIdx.x == 0) g_is64 = (s[0] == 0) ? 1 : 0;
}

__device__ __forceinline__ int load_src(const int* eil, int E, int e) {
    int v = g_is64 ? eil[2 * e] : eil[e];
    if ((unsigned)v >= (unsigned)MAXN) v = 0;   // defensive clamp (no wild accesses)
    return v;
}
__device__ __forceinline__ int load_dst(const int* eil, int E, int e) {
    int v = g_is64 ? eil[2 * (E + e)] : eil[E + e];
    if ((unsigned)v >= (unsigned)MAXN) v = 0;
    return v;
}

// ---------------- small utility kernels ----------------
__global__ void k_zero_cnt(int n) {
    int i = blockIdx.x * blockDim.x + threadIdx.x;
    if (i < n) g_cnt[i] = 0;
}

__global__ void k_hist(const int* __restrict__ eil, int E) {
    int e = blockIdx.x * blockDim.x + threadIdx.x;
    if (e >= E) return;
    int dst = load_dst(eil, E, e);
    atomicAdd(&g_cnt[dst], 1);
}

// ---------------- 3-level exclusive scan over g_cnt -> g_rs (256-thread blocks) ---
__global__ void k_scan_reduce(int n) {
    __shared__ int s[256];
    int i = blockIdx.x * 256 + threadIdx.x;
    s[threadIdx.x] = (i < n) ? g_cnt[i] : 0;
    __syncthreads();
    for (int off = 128; off > 0; off >>= 1) {
        if (threadIdx.x < off) s[threadIdx.x] += s[threadIdx.x + off];
        __syncthreads();
    }
    if (threadIdx.x == 0) g_bsums[blockIdx.x] = s[0];
}

__global__ void k_scan_sums(int nb) {
    int acc = 0;
    for (int i = 0; i < nb; i++) { int v = g_bsums[i]; g_bsums[i] = acc; acc += v; }
}

__global__ void k_scan_blocks(int n) {
    __shared__ int s[256];
    int tid = threadIdx.x;
    int i = blockIdx.x * 256 + tid;
    int v = (i < n) ? g_cnt[i] : 0;
    s[tid] = v;
    __syncthreads();
    for (int off = 1; off < 256; off <<= 1) {
        int t = (tid >= off) ? s[tid - off] : 0;
        __syncthreads();
        s[tid] += t;
        __syncthreads();
    }
    int excl = s[tid] - v + g_bsums[blockIdx.x];
    if (i < n) g_rs[i] = excl;            // exclusive start (pre-fill convention)
    if (i == n - 1) g_rs[n] = excl + v;
}

// ---------------- CSR fill: cursor IS g_rs (becomes row end) ----------------
__global__ void k_fill(const int* __restrict__ eil,
                       const float* __restrict__ ew,
                       const float* __restrict__ em1,
                       const float* __restrict__ em2, int E) {
    int e = blockIdx.x * blockDim.x + threadIdx.x;
    if (e >= E) return;
    int src = load_src(eil, E, e);
    int dst = load_dst(eil, E, e);
    float w0 = ew[e];
    int pos = atomicAdd(&g_rs[dst], 1);   // after kernel: g_rs[dst] = row end
    if ((unsigned)pos < (unsigned)MAXE) {
        int4 ent;
        ent.x = src;
        ent.y = __float_as_int(w0);
        ent.z = __float_as_int(w0 * em1[e]);
        ent.w = __float_as_int(w0 * em2[e]);
        g_ent[pos] = ent;
    }
}

// ---------------- per-view degree -> dinv (warp per node) ----------------
__global__ void k_dinv(int nn) {
    int gt = blockIdx.x * blockDim.x + threadIdx.x;
    int node = gt >> 5, lane = gt & 31;
    if (node >= nn) return;
    int s0 = (node == 0) ? 0 : g_rs[node - 1];
    int s1 = g_rs[node];
    float a0 = 0.f, a1 = 0.f, a2 = 0.f;
    for (int p = s0 + lane; p < s1; p += 32) {
        int4 e = g_ent[p];
        a0 += __int_as_float(e.y);
        a1 += __int_as_float(e.z);
        a2 += __int_as_float(e.w);
    }
    for (int off = 16; off > 0; off >>= 1) {
        a0 += __shfl_xor_sync(0xffffffffu, a0, off);
        a1 += __shfl_xor_sync(0xffffffffu, a1, off);
        a2 += __shfl_xor_sync(0xffffffffu, a2, off);
    }
    if (lane == 0) {
        g_d0[node] = rsqrtf(a0 + 1.0f);
        g_d1[node] = rsqrtf(a1 + 1.0f);
        g_d2[node] = rsqrtf(a2 + 1.0f);
    }
}

// ---------------- fold dinv[src] into stored edge weights ----------------
__global__ void k_coef(int totE) {
    int p = blockIdx.x * blockDim.x + threadIdx.x;
    if (p >= totE) return;
    int4 e = g_ent[p];
    int s = e.x;
    e.y = __float_as_int(__int_as_float(e.y) * g_d0[s]);
    e.z = __float_as_int(__int_as_float(e.z) * g_d1[s]);
    e.w = __float_as_int(__int_as_float(e.w) * g_d2[s]);
    g_ent[p] = e;
}

// ---------------- GEMM1: g_h[N][96] = x[N][512] @ Wc[512][96] ----------------
// Wc columns: [0:32)=W1, [32:64)=fm1*W1, [64:96)=fm2*W1 (mask along K rows).
// 256 threads, CTA tile 128x96, k-step 32, microtile 8x6.
// float4 A loads software-pipelined one k-step ahead (pure C++).
__global__ __launch_bounds__(256) void k_gemm1(const float* __restrict__ x,
                                               const float* __restrict__ W1,
                                               const float* __restrict__ fm1,
                                               const float* __restrict__ fm2,
                                               int M) {
    __shared__ float As[32][129];   // [k][row], padded: conflict-free
    __shared__ float Bs[32][NC];    // [k][col]
    int t = threadIdx.x;
    int mi = t & 15, ni = t >> 4;
    int rowbase = blockIdx.x * 128;

    // each thread's 4 A-load slots: row r, float4 column c4
    int rA[4], cA[4];
    #pragma unroll
    for (int i = 0; i < 4; i++) {
        int lin = t + i * 256;            // 0..1023 float4 slots
        rA[i] = lin >> 3;                 // 0..127
        cA[i] = lin & 7;                  // 0..7
    }

    float acc[8][6];
    #pragma unroll
    for (int i = 0; i < 8; i++)
        #pragma unroll
        for (int j = 0; j < 6; j++) acc[i][j] = 0.f;

    // prefetch k-step 0
    float4 pref[4];
    #pragma unroll
    for (int i = 0; i < 4; i++) {
        int row = rowbase + rA[i];
        pref[i] = make_float4(0.f, 0.f, 0.f, 0.f);
        if (row < M)
            pref[i] = *reinterpret_cast<const float4*>(x + (size_t)row * FDIM + cA[i] * 4);
    }

    #pragma unroll 1
    for (int ks = 0; ks < FDIM / 32; ks++) {
        int k0 = ks * 32;
        // commit prefetched A tile
        #pragma unroll
        for (int i = 0; i < 4; i++) {
            As[cA[i] * 4 + 0][rA[i]] = pref[i].x;
            As[cA[i] * 4 + 1][rA[i]] = pref[i].y;
            As[cA[i] * 4 + 2][rA[i]] = pref[i].z;
            As[cA[i] * 4 + 3][rA[i]] = pref[i].w;
        }
        // build B tile 32x96 (mask applied along K rows)
        #pragma unroll
        for (int i = 0; i < 12; i++) {
            int idx = t + i * 256;
            int kk = idx / NC, c = idx - kk * NC;
            int v = c >> 5;
            float m = (v == 0) ? 1.f : ((v == 1) ? fm1[k0 + kk] : fm2[k0 + kk]);
            Bs[kk][c] = m * W1[(k0 + kk) * HID + (c & 31)];
        }
        __syncthreads();
        // next k-step's global loads overlap the FMA block
        if (ks + 1 < FDIM / 32) {
            int kn = k0 + 32;
            #pragma unroll
            for (int i = 0; i < 4; i++) {
                int row = rowbase + rA[i];
                pref[i] = make_float4(0.f, 0.f, 0.f, 0.f);
                if (row < M)
                    pref[i] = *reinterpret_cast<const float4*>(
                        x + (size_t)row * FDIM + kn + cA[i] * 4);
            }
        }
        #pragma unroll
        for (int kk = 0; kk < 32; kk++) {
            float a[8], b[6];
            #pragma unroll
            for (int i = 0; i < 8; i++) a[i] = As[kk][i * 16 + mi];
            #pragma unroll
            for (int j = 0; j < 6; j++) b[j] = Bs[kk][ni * 6 + j];
            #pragma unroll
            for (int i = 0; i < 8; i++)
                #pragma unroll
                for (int j = 0; j < 6; j++)
                    acc[i][j] = fmaf(a[i], b[j], acc[i][j]);
        }
        __syncthreads();
    }
    #pragma unroll
    for (int i = 0; i < 8; i++) {
        int row = rowbase + i * 16 + mi;
        if (row < M) {
            float* op = g_h + (size_t)row * NC + ni * 6;
            #pragma unroll
            for (int j = 0; j < 6; j++) op[j] = acc[i][j];
        }
    }
}

// ---------------- GEMM2: g_h[n][v*32+j] = sum_jp g_z1[n][v*32+jp] * W2[jp][j] ------
__global__ __launch_bounds__(256) void k_gemm2(const float* __restrict__ W2, int nn) {
    __shared__ float W2s[HID * HID];
    __shared__ float zs[32 * NC];
    int t = threadIdx.x;
    for (int i = t; i < HID * HID; i += 256) W2s[i] = W2[i];
    int nbase = blockIdx.x * 32;
    for (int i = t; i < 32 * NC; i += 256) {
        int ln = i / NC, c = i - ln * NC;
        int row = nbase + ln;
        zs[i] = (row < nn) ? g_z1[(size_t)row * NC + c] : 0.f;
    }
    __syncthreads();
    for (int i = t; i < 32 * NC; i += 256) {
        int ln = i / NC, col = i - ln * NC;
        int v = col >> 5, j = col & 31;
        float acc = 0.f;
        #pragma unroll
        for (int jp = 0; jp < HID; jp++)
            acc += zs[ln * NC + v * 32 + jp] * W2s[jp * HID + j];
        int row = nbase + ln;
        if (row < nn) g_h[(size_t)row * NC + col] = acc;
    }
}

// ---------------- aggregation layer 1: g_z1 = relu(agg(g_h) + b1), [n][96] -------
__global__ __launch_bounds__(256) void k_agg1(const float* __restrict__ bias, int nn) {
    int gt = blockIdx.x * blockDim.x + threadIdx.x;
    int node = gt >> 5, lane = gt & 31;
    if (node >= nn) return;
    int s0 = (node == 0) ? 0 : g_rs[node - 1];
    int s1 = g_rs[node];
    float a0 = 0.f, a1 = 0.f, a2 = 0.f;
    #pragma unroll 4
    for (int p = s0; p < s1; p++) {
        int4 e = g_ent[p];                        // single 16B broadcast load
        const float* hp = g_h + (size_t)e.x * NC;
        a0 += __int_as_float(e.y) * hp[lane];
        a1 += __int_as_float(e.z) * hp[32 + lane];
        a2 += __int_as_float(e.w) * hp[64 + lane];
    }
    float d0 = g_d0[node], d1 = g_d1[node], d2 = g_d2[node];
    const float* hd = g_h + (size_t)node * NC;
    float b = bias[lane];
    float r0 = fmaxf(d0 * a0 + d0 * d0 * hd[lane]      + b, 0.f);
    float r1 = fmaxf(d1 * a1 + d1 * d1 * hd[32 + lane] + b, 0.f);
    float r2 = fmaxf(d2 * a2 + d2 * d2 * hd[64 + lane] + b, 0.f);
    g_z1[(size_t)node * NC + lane]      = r0;
    g_z1[(size_t)node * NC + 32 + lane] = r1;
    g_z1[(size_t)node * NC + 64 + lane] = r2;
}

// ---------------- aggregation layer 2: d_out = relu(agg(g_h) + b2), [v][n][32] ----
__global__ __launch_bounds__(256) void k_agg2(const float* __restrict__ bias,
                                              float* __restrict__ dout, int nn) {
    int gt = blockIdx.x * blockDim.x + threadIdx.x;
    int node = gt >> 5, lane = gt & 31;
    if (node >= nn) return;
    int s0 = (node == 0) ? 0 : g_rs[node - 1];
    int s1 = g_rs[node];
    float a0 = 0.f, a1 = 0.f, a2 = 0.f;
    #pragma unroll 4
    for (int p = s0; p < s1; p++) {
        int4 e = g_ent[p];
        const float* hp = g_h + (size_t)e.x * NC;
        a0 += __int_as_float(e.y) * hp[lane];
        a1 += __int_as_float(e.z) * hp[32 + lane];
        a2 += __int_as_float(e.w) * hp[64 + lane];
    }
    float d0 = g_d0[node], d1 = g_d1[node], d2 = g_d2[node];
    const float* hd = g_h + (size_t)node * NC;
    float b = bias[lane];
    float r0 = fmaxf(d0 * a0 + d0 * d0 * hd[lane]      + b, 0.f);
    float r1 = fmaxf(d1 * a1 + d1 * d1 * hd[32 + lane] + b, 0.f);
    float r2 = fmaxf(d2 * a2 + d2 * d2 * hd[64 + lane] + b, 0.f);
    size_t stride = (size_t)nn * 32;
    dout[0 * stride + (size_t)node * 32 + lane] = r0;
    dout[1 * stride + (size_t)node * 32 + lane] = r1;
    dout[2 * stride + (size_t)node * 32 + lane] = r2;
}

// ---------------- host orchestration ----------------
extern "C" void kernel_launch(void* const* d_in, const int* in_sizes, int n_in,
                              void* d_out, int out_size) {
    const float* x   = (const float*)d_in[0];
    const int*   eil = (const int*)d_in[1];     // edge_index as 32-bit words (dtype detected)
    const float* ew  = (const float*)d_in[2];
    const float* em1 = (const float*)d_in[3];
    const float* em2 = (const float*)d_in[4];
    const float* fm1 = (const float*)d_in[5];
    const float* fm2 = (const float*)d_in[6];
    const float* W1  = (const float*)d_in[7];
    const float* b1  = (const float*)d_in[8];
    const float* W2  = (const float*)d_in[9];
    const float* b2  = (const float*)d_in[10];
    float* out = (float*)d_out;

    int E  = in_sizes[2];              // edge_weight element count
    int nn = in_sizes[0] / FDIM;       // num nodes

    int eb  = (E + 255) / 256;
    int nb  = (nn + 255) / 256;
    int wb  = (nn * 32 + 255) / 256;   // warp-per-node grids

    // --- detect edge_index dtype, then CSR build ---
    k_detect<<<1, 256>>>(eil, E);
    k_zero_cnt<<<nb, 256>>>(nn);
    k_hist<<<eb, 256>>>(eil, E);
    k_scan_reduce<<<nb, 256>>>(nn);
    k_scan_sums<<<1, 1>>>(nb);
    k_scan_blocks<<<nb, 256>>>(nn);
    k_fill<<<eb, 256>>>(eil, ew, em1, em2, E);

    // --- degrees / dinv, then fold dinv[src] into weights ---
    k_dinv<<<wb, 256>>>(nn);
    k_coef<<<eb, 256>>>(E);

    // --- layer 1 ---
    k_gemm1<<<(nn + 127) / 128, 256>>>(x, W1, fm1, fm2, nn);
    k_agg1<<<wb, 256>>>(b1, nn);

    // --- layer 2 ---
    k_gemm2<<<(nn + 31) / 32, 256>>>(W2, nn);
    k_agg2<<<wb, 256>>>(b2, out, nn);
}